// round 5
// baseline (speedup 1.0000x reference)
#include <cuda_runtime.h>

#define BATCH 16
#define CH    64
#define HH    256
#define WW    256
#define M2    20
#define NRR   40
#define NIMG  (BATCH*CH)     /* 1024  */
#define NROW  (NIMG*HH)      /* 262144 */

// ---------------- scratch (device globals; no allocation allowed) ----------
__device__ float2 g_tw[256];          // e^{+2*pi*i*t/256}
__device__ float2 g_Y[NROW*M2];       // forward-W result  [img*256+h][k2]
__device__ float2 g_X[NIMG*NRR*M2];   // forward modes     [img][r][k2]
__device__ float2 g_O[NIMG*NRR*M2];   // mixed modes
__device__ float2 g_Z[NROW*M2];       // inverse-H result  [img*256+h][k2]
__device__ float2 g_W[800*4096];      // transposed weights [mode][i*64+o]  (26MB)

__global__ void init_tw() {
    int t = threadIdx.x;
    double a = 6.283185307179586476925286766559 * (double)t / 256.0;
    g_tw[t] = make_float2((float)cos(a), (float)sin(a));
}

// ---------------- stage 0: weight transpose --------------------------------
// A[u][off] = (wr[u*400+off], wi[u*400+off]), u=i*64+o in 0..4095, off=m1*20+k2 in 0..399
// -> g_W[(base+off)*4096 + u], base = 0 (w1) or 400 (w2)
__global__ __launch_bounds__(1024) void wtrans(const float* __restrict__ w1r, const float* __restrict__ w1i,
                                               const float* __restrict__ w2r, const float* __restrict__ w2i) {
    __shared__ float2 tile[32][33];
    const float* wr = blockIdx.z ? w2r : w1r;
    const float* wi = blockIdx.z ? w2i : w1i;
    int base = blockIdx.z ? 400 : 0;
    int tx = threadIdx.x, ty = threadIdx.y;
    int u0 = blockIdx.x * 32, o0 = blockIdx.y * 32;
    int off = o0 + tx;
    int u = u0 + ty;
    if (off < 400) tile[ty][tx] = make_float2(wr[u*400 + off], wi[u*400 + off]);
    __syncthreads();
    int offw = o0 + ty;
    if (offw < 400) g_W[(size_t)(base + offw)*4096 + u0 + tx] = tile[tx][ty];
}

// ---------------- stage 1: partial rfft along W ----------------------------
// Y[row][k2] = sum_w x[row][w] e^{-2pi i k2 w/256}, k2<20
// Fold: Re = x0 + (-1)^k2 x128 + sum_{w=1..127}(x_w+x_{256-w})cos(w th)
//       Im = -sum_{w=1..127}(x_w-x_{256-w})sin(w th)
// Block: 32 rows. Compute threads: 80; each does 4 rows x 2 bins off one
// twiddle-recurrence pair.
__global__ __launch_bounds__(256) void fwdW(const float* __restrict__ x) {
    __shared__ float2 seo[32*129];    // ~33KB, padded rows (bank spread)
    __shared__ float  x0s[32], xms[32];
    int t = threadIdx.x;
    const float* xb = x + (size_t)blockIdx.x * 8192;   // 32 rows x 256
    for (int i = t; i < 32*127; i += 256) {
        int row = i / 127, w = 1 + (i - row*127);
        float a = xb[row*256 + w], b = xb[row*256 + 256 - w];
        seo[row*129 + w] = make_float2(a + b, a - b);
    }
    if (t < 32)       x0s[t]      = xb[t*256];
    else if (t < 64)  xms[t - 32] = xb[(t - 32)*256 + 128];
    __syncthreads();
    if (t >= 80) return;
    int rr = t / 10, k2 = t - 10*rr;          // rr 0..7, k2 0..9
    float2 twa = g_tw[k2], twb = g_tw[k2 + 10];
    float ca1 = twa.x, sa1 = twa.y, cb1 = twb.x, sb1 = twb.y;
    float ca = ca1, sa = sa1, cb = cb1, sb = sb1;
    float arA[4] = {0,0,0,0}, aiA[4] = {0,0,0,0};
    float arB[4] = {0,0,0,0}, aiB[4] = {0,0,0,0};
    for (int w = 1; w < 128; ++w) {
        #pragma unroll
        for (int j = 0; j < 4; ++j) {
            float2 e = seo[(rr + 8*j)*129 + w];
            arA[j] = fmaf(e.x, ca, arA[j]);  aiA[j] = fmaf(e.y, sa, aiA[j]);
            arB[j] = fmaf(e.x, cb, arB[j]);  aiB[j] = fmaf(e.y, sb, aiB[j]);
        }
        float cn = fmaf(ca, ca1, -(sa*sa1)); sa = fmaf(sa, ca1, ca*sa1); ca = cn;
        float cm = fmaf(cb, cb1, -(sb*sb1)); sb = fmaf(sb, cb1, cb*sb1); cb = cm;
    }
    float sgn = (k2 & 1) ? -1.f : 1.f;        // parity of k2 == parity of k2+10
    #pragma unroll
    for (int j = 0; j < 4; ++j) {
        int row = rr + 8*j;
        size_t grow = (size_t)blockIdx.x*32 + row;
        float x0 = x0s[row], xm = xms[row];
        float reA = arA[j] + x0 + sgn*xm;
        float reB = arB[j] + x0 + sgn*xm;
        g_Y[grow*20 + k2]      = make_float2(reA, -aiA[j]);
        g_Y[grow*20 + k2 + 10] = make_float2(reB, -aiB[j]);
    }
}

// ---------------- stage 2: partial complex DFT along H ---------------------
// X[r][k2] = sum_h Y[h][k2] e^{-2pi i k1_r h/256}, k1_r = r<20 ? r : 216+r
__global__ __launch_bounds__(512) void fwdH() {
    __shared__ float2 Ys[HH*M2];   // 40KB
    int t = threadIdx.x, img = blockIdx.x;
    const float2* src = &g_Y[(size_t)img * HH * M2];
    for (int i = t; i < HH*M2; i += 512) Ys[i] = src[i];
    __syncthreads();
    if (t >= 400) return;
    int r = t / 10, k2 = t - 10*(t/10);
    int k1 = r + (r >= 20 ? 216 : 0);
    float2 tw = g_tw[k1];
    float c1 = tw.x, s1 = -tw.y;          // step e^{-i th}
    float c = 1.f, s = 0.f;
    float Xr0 = 0.f, Xi0 = 0.f, Xr1 = 0.f, Xi1 = 0.f;
    for (int h = 0; h < HH; ++h) {
        float2 y0 = Ys[h*20 + k2];
        float2 y1 = Ys[h*20 + k2 + 10];
        Xr0 = fmaf(y0.x, c, Xr0);  Xr0 = fmaf(-y0.y, s, Xr0);
        Xi0 = fmaf(y0.y, c, Xi0);  Xi0 = fmaf(y0.x, s, Xi0);
        Xr1 = fmaf(y1.x, c, Xr1);  Xr1 = fmaf(-y1.y, s, Xr1);
        Xi1 = fmaf(y1.y, c, Xi1);  Xi1 = fmaf(y1.x, s, Xi1);
        float cn = fmaf(c, c1, -(s*s1));
        s = fmaf(s, c1, c*s1);
        c = cn;
    }
    g_X[(size_t)img*800 + r*20 + k2]      = make_float2(Xr0, Xi0);
    g_X[(size_t)img*800 + r*20 + k2 + 10] = make_float2(Xr1, Xi1);
}

// ---------------- stage 3: per-mode complex channel mixing -----------------
// O[b][o][mode] = sum_i X[b][i][mode] * W[i][o][mode]  (complex)
// Weights come pre-transposed (g_W, coalesced). Each thread: 4 b's, one o.
__global__ __launch_bounds__(256) void mixk() {
    __shared__ float2 Xs[1024];   // [b*64+i]
    __shared__ float2 Ws[4096];   // [i*64+o]
    int t = threadIdx.x, mo = blockIdx.x;
    for (int u = t; u < 1024; u += 256) Xs[u] = g_X[(size_t)u*800 + mo];
    const float4* wsrc = (const float4*)&g_W[(size_t)mo*4096];
    for (int u = t; u < 2048; u += 256) ((float4*)Ws)[u] = wsrc[u];
    __syncthreads();
    int o = t & 63, b0 = t >> 6;
    float ar[4] = {0,0,0,0}, ai[4] = {0,0,0,0};
    for (int i = 0; i < 64; ++i) {
        float2 Wv = Ws[i*64 + o];
        #pragma unroll
        for (int j = 0; j < 4; ++j) {
            float2 X = Xs[(b0 + 4*j)*64 + i];
            ar[j] = fmaf(X.x, Wv.x, ar[j]);  ar[j] = fmaf(-X.y, Wv.y, ar[j]);
            ai[j] = fmaf(X.x, Wv.y, ai[j]);  ai[j] = fmaf(X.y, Wv.x, ai[j]);
        }
    }
    #pragma unroll
    for (int j = 0; j < 4; ++j) {
        int u = (b0 + 4*j)*64 + o;
        g_O[(size_t)u*800 + mo] = make_float2(ar[j], ai[j]);
    }
}

// ---------------- stage 4: inverse DFT along H -----------------------------
// Z[h][k2] = sum_r O[r][k2] e^{+2pi i k1_r h/256}   (no 1/H yet)
__global__ __launch_bounds__(256) void invH() {
    __shared__ float2 Os[800];
    __shared__ float2 Zst[HH*M2];   // 40KB staging for coalesced store
    int t = threadIdx.x, img = blockIdx.x;
    const float2* src = &g_O[(size_t)img*800];
    for (int i = t; i < 800; i += 256) Os[i] = src[i];
    __syncthreads();
    int h = t;
    float2 tw = g_tw[h];
    float ch = tw.x, sh = tw.y;   // step e^{+i phi}, phi = 2pi h/256
    float Zr[20], Zi[20];
    #pragma unroll
    for (int k = 0; k < 20; ++k) { Zr[k] = 0.f; Zi[k] = 0.f; }
    float c = 1.f, s = 0.f;
    for (int rr = 0; rr < 20; ++rr) {              // k1 = 0..19
        #pragma unroll
        for (int k = 0; k < 20; ++k) {
            float2 O = Os[rr*20 + k];
            Zr[k] = fmaf(O.x, c, Zr[k]);  Zr[k] = fmaf(-O.y, s, Zr[k]);
            Zi[k] = fmaf(O.y, c, Zi[k]);  Zi[k] = fmaf(O.x, s, Zi[k]);
        }
        float cn = fmaf(c, ch, -(s*sh)); s = fmaf(s, ch, c*sh); c = cn;
    }
    float c2 = c, s2 = -s;                          // e^{-i*20 phi} == k1 = 236
    for (int rr = 20; rr < 40; ++rr) {             // k1 = 236..255
        #pragma unroll
        for (int k = 0; k < 20; ++k) {
            float2 O = Os[rr*20 + k];
            Zr[k] = fmaf(O.x, c2, Zr[k]);  Zr[k] = fmaf(-O.y, s2, Zr[k]);
            Zi[k] = fmaf(O.y, c2, Zi[k]);  Zi[k] = fmaf(O.x, s2, Zi[k]);
        }
        float cn = fmaf(c2, ch, -(s2*sh)); s2 = fmaf(s2, ch, c2*sh); c2 = cn;
    }
    #pragma unroll
    for (int k = 0; k < 20; ++k) Zst[h*20 + k] = make_float2(Zr[k], Zi[k]);
    __syncthreads();
    float2* dst = &g_Z[(size_t)img * HH * M2];
    for (int i = t; i < HH*M2; i += 256) dst[i] = Zst[i];
}

// ---------------- stage 5: inverse real DFT along W ------------------------
// out[w]     = (ReZ0 + 2*sum_{k=1..19}(ReZ c - ImZ s)) / 65536
// out[256-w] = (ReZ0 + 2*sum_{k=1..19}(ReZ c + ImZ s)) / 65536
// Block: 8 rows; each thread: one wl, 4 rows off one recurrence.
__global__ __launch_bounds__(256) void invW(float* __restrict__ out) {
    __shared__ float2 Zs[8*20];
    int t = threadIdx.x;
    for (int i = t; i < 160; i += 256) Zs[i] = g_Z[(size_t)blockIdx.x*160 + i];
    __syncthreads();
    int rg = t >> 7, wl = t & 127;       // rg 0..1 -> rows rg*4 .. rg*4+3
    float2 tw = g_tw[wl];
    float cw = tw.x, sw = tw.y, c = cw, s = sw;
    float A[4] = {0,0,0,0}, Bv[4] = {0,0,0,0};
    #pragma unroll
    for (int k = 1; k < 20; ++k) {
        #pragma unroll
        for (int j = 0; j < 4; ++j) {
            float2 Z = Zs[(rg*4 + j)*20 + k];
            A[j]  = fmaf(Z.x, c, A[j]);
            Bv[j] = fmaf(Z.y, s, Bv[j]);
        }
        float cn = fmaf(c, cw, -(s*sw)); s = fmaf(s, cw, c*sw); c = cn;
    }
    const float SC = 1.f / 65536.f;
    #pragma unroll
    for (int j = 0; j < 4; ++j) {
        int row = rg*4 + j;
        float base = Zs[row*20].x;       // Im of DC bin ignored (Hermitian semantics)
        float* orow = out + ((size_t)blockIdx.x*8 + row)*256;
        orow[wl] = (base + 2.f*(A[j] - Bv[j])) * SC;
        if (wl) {
            orow[256 - wl] = (base + 2.f*(A[j] + Bv[j])) * SC;
        } else {
            float acc = 0.f, sg = -1.f;  // w = 128: cos(pi k) = (-1)^k, sin = 0
            #pragma unroll
            for (int k = 1; k < 20; ++k) { acc = fmaf(sg, Zs[row*20 + k].x, acc); sg = -sg; }
            orow[128] = (base + 2.f*acc) * SC;
        }
    }
}

extern "C" void kernel_launch(void* const* d_in, const int* in_sizes, int n_in,
                              void* d_out, int out_size) {
    const float* x   = (const float*)d_in[0];
    const float* w1r = (const float*)d_in[1];
    const float* w1i = (const float*)d_in[2];
    const float* w2r = (const float*)d_in[3];
    const float* w2i = (const float*)d_in[4];
    float* out = (float*)d_out;

    init_tw<<<1, 256>>>();
    wtrans<<<dim3(128, 13, 2), dim3(32, 32)>>>(w1r, w1i, w2r, w2i);
    fwdW<<<NROW/32, 256>>>(x);
    fwdH<<<NIMG, 512>>>();
    mixk<<<NRR*M2, 256>>>();
    invH<<<NIMG, 256>>>();
    invW<<<NROW/8, 256>>>(out);
}

// round 6
// speedup vs baseline: 1.4150x; 1.4150x over previous
#include <cuda_runtime.h>

#define BATCH 16
#define CH    64
#define HH    256
#define WW    256
#define M2    20
#define NRR   40
#define NIMG  (BATCH*CH)     /* 1024  */
#define NROW  (NIMG*HH)      /* 262144 */

// ---------------- scratch (device globals; no allocation allowed) ----------
__device__ float2 g_tw[256];          // e^{+2*pi*i*t/256}
__device__ float2 g_Y[NROW*M2];       // forward-W result  [img*256+h][k2]
__device__ float2 g_X[NIMG*NRR*M2];   // forward modes     [img][r][k2]
__device__ float2 g_O[NIMG*NRR*M2];   // mixed modes
__device__ float2 g_Z[NROW*M2];       // inverse-H result  [img*256+h][k2]
__device__ float2 g_W[800*4096];      // transposed weights [mode][i*64+o]

__global__ void init_tw() {
    int t = threadIdx.x;
    double a = 6.283185307179586476925286766559 * (double)t / 256.0;
    g_tw[t] = make_float2((float)cos(a), (float)sin(a));
}

// ---------------- stage 0: weight transpose --------------------------------
__global__ __launch_bounds__(1024) void wtrans(const float* __restrict__ w1r, const float* __restrict__ w1i,
                                               const float* __restrict__ w2r, const float* __restrict__ w2i) {
    __shared__ float2 tile[32][33];
    const float* wr = blockIdx.z ? w2r : w1r;
    const float* wi = blockIdx.z ? w2i : w1i;
    int base = blockIdx.z ? 400 : 0;
    int tx = threadIdx.x, ty = threadIdx.y;
    int u0 = blockIdx.x * 32, o0 = blockIdx.y * 32;
    int off = o0 + tx;
    int u = u0 + ty;
    if (off < 400) tile[ty][tx] = make_float2(wr[u*400 + off], wi[u*400 + off]);
    __syncthreads();
    int offw = o0 + ty;
    if (offw < 400) g_W[(size_t)(base + offw)*4096 + u0 + tx] = tile[tx][ty];
}

// ---------------- stage 1: partial rfft along W (double fold) --------------
// Re_k = x0 + (-1)^k x128 + s64*cos(k pi/2) + sum_{w=1..63} (even? sp : sm) cos(kw th)
// Im_k = -( d64*sin(k pi/2) + sum_{w=1..63} (even? dm : dp) sin(kw th) )
// sp=s_w+s_{128-w}, sm=s_w-s_{128-w}, dp=d_w+d_{128-w}, dm=d_w-d_{128-w},
// s_w=x_w+x_{256-w}, d_w=x_w-x_{256-w}.
__global__ __launch_bounds__(160) void fwdW(const float* __restrict__ x) {
    __shared__ float2 SAB[2*2080 + 2];   // SA rows stride 65; SB at +2082 (bank shift)
    __shared__ float4 SP[32];            // (x0, x128, s64, d64) per row
    float2* SA = SAB;
    float2* SB = SAB + 2082;
    int t = threadIdx.x;
    const float* xb = x + (size_t)blockIdx.x * 8192;   // 32 rows x 256
    for (int i = t; i < 32*63; i += 160) {
        int row = i / 63, w = 1 + (i - row*63);
        const float* xr = xb + row*256;
        float a = xr[w], b = xr[256 - w], cc = xr[128 - w], dd = xr[128 + w];
        float s = a + b, d = a - b, s2 = cc + dd, d2 = cc - dd;
        SA[row*65 + w] = make_float2(s + s2, d - d2);   // (sp, dm)
        SB[row*65 + w] = make_float2(s - s2, d + d2);   // (sm, dp)
    }
    if (t < 32) {
        const float* xr = xb + t*256;
        float x64 = xr[64], x192 = xr[192];
        SP[t] = make_float4(xr[0], xr[128], x64 + x192, x64 - x192);
    }
    __syncthreads();
    int rr = t / 20, k2 = t - 20*rr;          // rr 0..7, k2 0..19
    int oddk = k2 & 1;
    const float2* base = oddk ? SB : SA;
    float f4 = (k2 & 2) ? -1.f : 1.f;         // cos/sin(k pi/2) magnitude sign
    float2 tw = g_tw[k2];
    float c1 = tw.x, s1 = tw.y, c = c1, s = s1;   // start at w=1
    float ar[4] = {0,0,0,0}, ai[4] = {0,0,0,0};
    for (int w = 1; w < 64; ++w) {
        #pragma unroll
        for (int j = 0; j < 4; ++j) {
            float2 e = base[(rr + 8*j)*65 + w];
            ar[j] = fmaf(e.x, c, ar[j]);
            ai[j] = fmaf(e.y, s, ai[j]);
        }
        float cn = fmaf(c, c1, -(s*s1)); s = fmaf(s, c1, c*s1); c = cn;
    }
    #pragma unroll
    for (int j = 0; j < 4; ++j) {
        int row = rr + 8*j;
        float4 sp = SP[row];
        float re, im;
        if (oddk) { re = ar[j] + sp.x - sp.y;             im = -(ai[j] + f4*sp.w); }
        else      { re = ar[j] + sp.x + sp.y + f4*sp.z;   im = -ai[j]; }
        g_Y[((size_t)blockIdx.x*32 + row)*20 + k2] = make_float2(re, im);
    }
}

// ---------------- stage 2: partial complex DFT along H (h-fold) ------------
// X_k1 = sum_{h=0..127} (Y_h + (-1)^k1 Y_{h+128}) e^{-i k1 h th}
__global__ __launch_bounds__(512) void fwdH() {
    __shared__ float2 Ys[5122];     // Yp at [0,2560), Ym at [2562,5122)
    int t = threadIdx.x, img = blockIdx.x;
    const float2* src = &g_Y[(size_t)img * HH * M2];
    for (int i = t; i < HH*M2; i += 512) {
        int d = (i < 2560) ? i : i + 2;
        Ys[d] = src[i];
    }
    __syncthreads();
    // butterfly in place: Yp -> [i], Ym -> [2562+i]
    for (int i = t; i < 2560; i += 512) {
        float2 a = Ys[i], b = Ys[2562 + i];
        Ys[i]        = make_float2(a.x + b.x, a.y + b.y);
        Ys[2562 + i] = make_float2(a.x - b.x, a.y - b.y);
    }
    __syncthreads();
    if (t >= 400) return;
    int r = t / 10, j = t - 10*(t/10);
    int k1 = r + (r >= 20 ? 216 : 0);
    const float2* base = (r & 1) ? (Ys + 2562) : Ys;
    float2 tw = g_tw[k1];
    float c1 = tw.x, s1 = -tw.y;          // step e^{-i th}
    float c = 1.f, s = 0.f;
    float Xr0 = 0.f, Xi0 = 0.f, Xr1 = 0.f, Xi1 = 0.f;
    for (int h = 0; h < 128; ++h) {
        float2 y0 = base[h*20 + j];
        float2 y1 = base[h*20 + j + 10];
        Xr0 = fmaf(y0.x, c, Xr0);  Xr0 = fmaf(-y0.y, s, Xr0);
        Xi0 = fmaf(y0.y, c, Xi0);  Xi0 = fmaf(y0.x, s, Xi0);
        Xr1 = fmaf(y1.x, c, Xr1);  Xr1 = fmaf(-y1.y, s, Xr1);
        Xi1 = fmaf(y1.y, c, Xi1);  Xi1 = fmaf(y1.x, s, Xi1);
        float cn = fmaf(c, c1, -(s*s1)); s = fmaf(s, c1, c*s1); c = cn;
    }
    g_X[(size_t)img*800 + r*20 + j]      = make_float2(Xr0, Xi0);
    g_X[(size_t)img*800 + r*20 + j + 10] = make_float2(Xr1, Xi1);
}

// ---------------- stage 3: per-mode complex channel mixing -----------------
__global__ __launch_bounds__(256) void mixk() {
    __shared__ float2 Xs[1024];   // [b*64+i]
    __shared__ float2 Ws[4096];   // [i*64+o]
    int t = threadIdx.x, mo = blockIdx.x;
    for (int u = t; u < 1024; u += 256) Xs[u] = g_X[(size_t)u*800 + mo];
    const float4* wsrc = (const float4*)&g_W[(size_t)mo*4096];
    for (int u = t; u < 2048; u += 256) ((float4*)Ws)[u] = wsrc[u];
    __syncthreads();
    int o = t & 63, b0 = t >> 6;
    float ar[4] = {0,0,0,0}, ai[4] = {0,0,0,0};
    for (int i = 0; i < 64; ++i) {
        float2 Wv = Ws[i*64 + o];
        #pragma unroll
        for (int j = 0; j < 4; ++j) {
            float2 X = Xs[(b0 + 4*j)*64 + i];
            ar[j] = fmaf(X.x, Wv.x, ar[j]);  ar[j] = fmaf(-X.y, Wv.y, ar[j]);
            ai[j] = fmaf(X.x, Wv.y, ai[j]);  ai[j] = fmaf(X.y, Wv.x, ai[j]);
        }
    }
    #pragma unroll
    for (int j = 0; j < 4; ++j) {
        int u = (b0 + 4*j)*64 + o;
        g_O[(size_t)u*800 + mo] = make_float2(ar[j], ai[j]);
    }
}

// ---------------- stage 4: inverse DFT along H (parity split) --------------
// Ze = sum_{r even} O_r e^{+i k1 h th}, Zo = sum_{r odd};
// Z_h = Ze + Zo, Z_{h+128} = Ze - Zo.
__global__ __launch_bounds__(256) void invH() {
    __shared__ float2 Os[800];
    __shared__ float2 Zst[HH*M2];   // 40KB staging
    int t = threadIdx.x, img = blockIdx.x;
    const float2* src = &g_O[(size_t)img*800];
    for (int i = t; i < 800; i += 256) Os[i] = src[i];
    __syncthreads();
    int g = t >> 7, h = t & 127;         // g: k2 group (0..1), h: 0..127
    int kb = g*10;
    float2 st = g_tw[(2*h) & 255];       // step e^{+i 2h th}
    float stc = st.x, sts = st.y;
    float Zer[10], Zei[10], Zor[10], Zoi[10];
    #pragma unroll
    for (int k = 0; k < 10; ++k) { Zer[k]=0.f; Zei[k]=0.f; Zor[k]=0.f; Zoi[k]=0.f; }

    // even chain: k1 = 0,2,..,18 then 236,..,254 (r = 0,2,..,18, 20,22,..,38)
    {
        float c = 1.f, s = 0.f;
        #pragma unroll
        for (int rr = 0; rr < 10; ++rr) {
            int r = 2*rr;
            #pragma unroll
            for (int k = 0; k < 10; ++k) {
                float2 O = Os[r*20 + kb + k];
                Zer[k] = fmaf(O.x, c, Zer[k]);  Zer[k] = fmaf(-O.y, s, Zer[k]);
                Zei[k] = fmaf(O.y, c, Zei[k]);  Zei[k] = fmaf(O.x, s, Zei[k]);
            }
            float cn = fmaf(c, stc, -(s*sts)); s = fmaf(s, stc, c*sts); c = cn;
        }
        s = -s;   // phase now e^{+i20h th}; conj -> e^{-i20h th} = e^{+i236h th}
        #pragma unroll
        for (int rr = 0; rr < 10; ++rr) {
            int r = 20 + 2*rr;
            #pragma unroll
            for (int k = 0; k < 10; ++k) {
                float2 O = Os[r*20 + kb + k];
                Zer[k] = fmaf(O.x, c, Zer[k]);  Zer[k] = fmaf(-O.y, s, Zer[k]);
                Zei[k] = fmaf(O.y, c, Zei[k]);  Zei[k] = fmaf(O.x, s, Zei[k]);
            }
            float cn = fmaf(c, stc, -(s*sts)); s = fmaf(s, stc, c*sts); c = cn;
        }
    }
    // odd chain: k1 = 1,3,..,19 then 237,..,255 (r = 1,3,..,19, 21,..,39)
    {
        float2 t1 = g_tw[h];
        float c = t1.x, s = t1.y;         // e^{+i h th} (k1=1)
        #pragma unroll
        for (int rr = 0; rr < 10; ++rr) {
            int r = 1 + 2*rr;
            #pragma unroll
            for (int k = 0; k < 10; ++k) {
                float2 O = Os[r*20 + kb + k];
                Zor[k] = fmaf(O.x, c, Zor[k]);  Zor[k] = fmaf(-O.y, s, Zor[k]);
                Zoi[k] = fmaf(O.y, c, Zoi[k]);  Zoi[k] = fmaf(O.x, s, Zoi[k]);
            }
            if (rr < 9) { float cn = fmaf(c, stc, -(s*sts)); s = fmaf(s, stc, c*sts); c = cn; }
        }
        s = -s;   // phase at e^{+i19h th}; conj -> e^{+i237h th}
        #pragma unroll
        for (int rr = 0; rr < 10; ++rr) {
            int r = 21 + 2*rr;
            #pragma unroll
            for (int k = 0; k < 10; ++k) {
                float2 O = Os[r*20 + kb + k];
                Zor[k] = fmaf(O.x, c, Zor[k]);  Zor[k] = fmaf(-O.y, s, Zor[k]);
                Zoi[k] = fmaf(O.y, c, Zoi[k]);  Zoi[k] = fmaf(O.x, s, Zoi[k]);
            }
            float cn = fmaf(c, stc, -(s*sts)); s = fmaf(s, stc, c*sts); c = cn;
        }
    }
    #pragma unroll
    for (int k = 0; k < 10; ++k) {
        Zst[h*20 + kb + k]         = make_float2(Zer[k] + Zor[k], Zei[k] + Zoi[k]);
        Zst[(h + 128)*20 + kb + k] = make_float2(Zer[k] - Zor[k], Zei[k] - Zoi[k]);
    }
    __syncthreads();
    float2* dst = &g_Z[(size_t)img * HH * M2];
    for (int i = t; i < HH*M2; i += 256) dst[i] = Zst[i];
}

// ---------------- stage 5: inverse real DFT along W (k-parity fold) --------
// Ae/Ao = sum_{k even/odd} Zr_k cos(kw th); Be/Bo likewise with Zi sin.
// out[w]=Zr0+2(Ae+Ao-Be-Bo); out[256-w]=Zr0+2(Ae+Ao+Be+Bo);
// out[128-w]=Zr0+2(Ae-Ao+Be-Bo); out[128+w]=Zr0+2(Ae-Ao-Be+Bo).  (x SC)
__global__ __launch_bounds__(256) void invW(float* __restrict__ out) {
    __shared__ float2 Zs[16*20];
    int t = threadIdx.x;
    for (int i = t; i < 320; i += 256) Zs[i] = g_Z[(size_t)blockIdx.x*320 + i];
    __syncthreads();
    int rg = t >> 6, wl = t & 63;        // rg 0..3 -> rows rg*4..rg*4+3
    float2 tw = g_tw[wl];
    float cw = tw.x, sw = tw.y, c = cw, s = sw;   // phase k=1
    float Ae[4]={0,0,0,0}, Ao[4]={0,0,0,0}, Be[4]={0,0,0,0}, Bo[4]={0,0,0,0};
    #pragma unroll
    for (int k = 1; k < 20; ++k) {
        if (k & 1) {
            #pragma unroll
            for (int j = 0; j < 4; ++j) {
                float2 Z = Zs[(rg*4 + j)*20 + k];
                Ao[j] = fmaf(Z.x, c, Ao[j]);
                Bo[j] = fmaf(Z.y, s, Bo[j]);
            }
        } else {
            #pragma unroll
            for (int j = 0; j < 4; ++j) {
                float2 Z = Zs[(rg*4 + j)*20 + k];
                Ae[j] = fmaf(Z.x, c, Ae[j]);
                Be[j] = fmaf(Z.y, s, Be[j]);
            }
        }
        float cn = fmaf(c, cw, -(s*sw)); s = fmaf(s, cw, c*sw); c = cn;
    }
    const float SC = 1.f / 65536.f;
    #pragma unroll
    for (int j = 0; j < 4; ++j) {
        int row = rg*4 + j;
        float base = Zs[row*20].x;       // Im of DC bin ignored (Hermitian)
        float* orow = out + ((size_t)blockIdx.x*16 + row)*256;
        float ap = Ae[j] + Ao[j], am = Ae[j] - Ao[j];
        float bp = Be[j] + Bo[j], bm = Be[j] - Bo[j];
        orow[wl]      = (base + 2.f*(ap - bp)) * SC;            // w (wl=0 -> out[0])
        orow[128-wl]  = (base + 2.f*(am + bm)) * SC;            // 128-w (wl=0 -> out[128])
        if (wl) {
            orow[256-wl] = (base + 2.f*(ap + bp)) * SC;         // 256-w
            orow[128+wl] = (base + 2.f*(am - bm)) * SC;         // 128+w
        } else {
            // out[64], out[192]: cos(k pi/2), sin(k pi/2) pattern
            float a64 = 0.f, b64 = 0.f;
            #pragma unroll
            for (int k = 1; k < 20; ++k) {
                float2 Z = Zs[row*20 + k];
                int m = k & 3;
                if (m == 0)      a64 += Z.x;
                else if (m == 2) a64 -= Z.x;
                else if (m == 1) b64 += Z.y;
                else             b64 -= Z.y;
            }
            orow[64]  = (base + 2.f*(a64 - b64)) * SC;
            orow[192] = (base + 2.f*(a64 + b64)) * SC;
        }
    }
}

extern "C" void kernel_launch(void* const* d_in, const int* in_sizes, int n_in,
                              void* d_out, int out_size) {
    const float* x   = (const float*)d_in[0];
    const float* w1r = (const float*)d_in[1];
    const float* w1i = (const float*)d_in[2];
    const float* w2r = (const float*)d_in[3];
    const float* w2i = (const float*)d_in[4];
    float* out = (float*)d_out;

    init_tw<<<1, 256>>>();
    wtrans<<<dim3(128, 13, 2), dim3(32, 32)>>>(w1r, w1i, w2r, w2i);
    fwdW<<<NROW/32, 160>>>(x);
    fwdH<<<NIMG, 512>>>();
    mixk<<<NRR*M2, 256>>>();
    invH<<<NIMG, 256>>>();
    invW<<<NROW/16, 256>>>(out);
}

// round 8
// speedup vs baseline: 1.4162x; 1.0009x over previous
#include <cuda_runtime.h>

#define BATCH 16
#define CH    64
#define HH    256
#define WW    256
#define M2    20
#define NRR   40
#define NIMG  (BATCH*CH)     /* 1024  */
#define NROW  (NIMG*HH)      /* 262144 */

// ---------------- scratch (device globals; no allocation allowed) ----------
__device__ float2 g_tw[256];          // e^{+2*pi*i*t/256}
__device__ float2 g_basIW[19*64];     // invW basis: [k-1][wl] = (cos, sin)(2pi k wl/256)
__device__ float2 g_Y[NROW*M2];       // forward-W result  [img*256+h][k2]
__device__ float2 g_X[NIMG*NRR*M2];   // forward modes     [img][r][k2]
__device__ float2 g_O[NIMG*NRR*M2];   // mixed modes
__device__ float2 g_Z[NROW*M2];       // inverse-H result  [img*256+h][k2]
__device__ float2 g_W[800*4096];      // transposed weights [mode][i*64+o]

// ---------------- stage 0: weight transpose + table init -------------------
__global__ __launch_bounds__(1024) void wtrans(const float* __restrict__ w1r, const float* __restrict__ w1i,
                                               const float* __restrict__ w2r, const float* __restrict__ w2i) {
    __shared__ float2 tile[32][33];
    int tx = threadIdx.x, ty = threadIdx.y;
    int tid = ty*32 + tx;
    if (blockIdx.x == 0 && blockIdx.y == 0 && blockIdx.z == 0) {
        if (tid < 256) {
            double a = 6.283185307179586476925286766559 * (double)tid / 256.0;
            g_tw[tid] = make_float2((float)cos(a), (float)sin(a));
        }
        for (int i = tid; i < 19*64; i += 1024) {
            int k = (i >> 6) + 1, wl = i & 63;
            double a = 6.283185307179586476925286766559 * (double)(k*wl) / 256.0;
            g_basIW[i] = make_float2((float)cos(a), (float)sin(a));
        }
    }
    const float* wr = blockIdx.z ? w2r : w1r;
    const float* wi = blockIdx.z ? w2i : w1i;
    int base = blockIdx.z ? 400 : 0;
    int u0 = blockIdx.x * 32, o0 = blockIdx.y * 32;
    int off = o0 + tx;
    int u = u0 + ty;
    if (off < 400) tile[ty][tx] = make_float2(wr[u*400 + off], wi[u*400 + off]);
    __syncthreads();
    int offw = o0 + ty;
    if (offw < 400) g_W[(size_t)(base + offw)*4096 + u0 + tx] = tile[tx][ty];
}

// ---------------- stage 1: partial rfft along W (double fold) --------------
__global__ __launch_bounds__(160) void fwdW(const float* __restrict__ x) {
    __shared__ float2 SAB[2*2080 + 2];   // SA rows stride 65; SB at +2082 (bank shift)
    __shared__ float4 SP[32];            // (x0, x128, s64, d64) per row
    float2* SA = SAB;
    float2* SB = SAB + 2082;
    int t = threadIdx.x;
    const float* xb = x + (size_t)blockIdx.x * 8192;   // 32 rows x 256
    for (int i = t; i < 32*63; i += 160) {
        int row = i / 63, w = 1 + (i - row*63);
        const float* xr = xb + row*256;
        float a = xr[w], b = xr[256 - w], cc = xr[128 - w], dd = xr[128 + w];
        float s = a + b, d = a - b, s2 = cc + dd, d2 = cc - dd;
        SA[row*65 + w] = make_float2(s + s2, d - d2);   // (sp, dm)
        SB[row*65 + w] = make_float2(s - s2, d + d2);   // (sm, dp)
    }
    if (t < 32) {
        const float* xr = xb + t*256;
        float x64 = xr[64], x192 = xr[192];
        SP[t] = make_float4(xr[0], xr[128], x64 + x192, x64 - x192);
    }
    __syncthreads();
    int rr = t / 20, k2 = t - 20*rr;          // rr 0..7, k2 0..19
    int oddk = k2 & 1;
    const float2* base = oddk ? SB : SA;
    float f4 = (k2 & 2) ? -1.f : 1.f;
    float2 tw = g_tw[k2];
    float c1 = tw.x, s1 = tw.y, c = c1, s = s1;   // start at w=1
    float ar[4] = {0,0,0,0}, ai[4] = {0,0,0,0};
    for (int w = 1; w < 64; ++w) {
        #pragma unroll
        for (int j = 0; j < 4; ++j) {
            float2 e = base[(rr + 8*j)*65 + w];
            ar[j] = fmaf(e.x, c, ar[j]);
            ai[j] = fmaf(e.y, s, ai[j]);
        }
        float cn = fmaf(c, c1, -(s*s1)); s = fmaf(s, c1, c*s1); c = cn;
    }
    #pragma unroll
    for (int j = 0; j < 4; ++j) {
        int row = rr + 8*j;
        float4 sp = SP[row];
        float re, im;
        if (oddk) { re = ar[j] + sp.x - sp.y;             im = -(ai[j] + f4*sp.w); }
        else      { re = ar[j] + sp.x + sp.y + f4*sp.z;   im = -ai[j]; }
        g_Y[((size_t)blockIdx.x*32 + row)*20 + k2] = make_float2(re, im);
    }
}

// ---------------- stage 2: partial complex DFT along H (radix-4 h-fold) ----
// h = h' + 64m; omega^64 = -i; class q = k1 mod 4 = r mod 4 (216 % 4 == 0).
// C_q[h'] = sum_m ((-i)^q)^m Y_{h'+64m};  X_k1 = sum_{h'=0..63} C_q[h'] e^{-i k1 h' th}
__global__ __launch_bounds__(256) void fwdH() {
    __shared__ float2 Ys[4*1288];   // 4 classes, padded stride 1288 (bank offset 8)
    int t = threadIdx.x, img = blockIdx.x;
    const float2* src = &g_Y[(size_t)img * 5120];
    for (int i = t; i < 5120; i += 256) {
        int m = i / 1280, rsd = i - m*1280;
        Ys[m*1288 + rsd] = src[i];
    }
    __syncthreads();
    for (int i = t; i < 1280; i += 256) {
        float2 a0 = Ys[i], a1 = Ys[1288 + i], a2 = Ys[2576 + i], a3 = Ys[3864 + i];
        float Ax = a0.x - a2.x, Ay = a0.y - a2.y;
        float Bx = a1.x - a3.x, By = a1.y - a3.y;
        float Sx = a0.x + a2.x, Sy = a0.y + a2.y;
        float Tx = a1.x + a3.x, Ty = a1.y + a3.y;
        Ys[i]        = make_float2(Sx + Tx, Sy + Ty);   // q=0: Y0+Y1+Y2+Y3
        Ys[1288 + i] = make_float2(Ax + By, Ay - Bx);   // q=1: A - iB
        Ys[2576 + i] = make_float2(Sx - Tx, Sy - Ty);   // q=2: Y0-Y1+Y2-Y3
        Ys[3864 + i] = make_float2(Ax - By, Ay + Bx);   // q=3: A + iB
    }
    __syncthreads();
    if (t >= 200) return;
    int r = t / 5, j0 = t - 5*(t/5);          // r 0..39, j0 0..4
    int k1 = r + (r >= 20 ? 216 : 0);
    const float2* base = Ys + (r & 3)*1288 + j0;
    float2 tw = g_tw[k1];
    float c1 = tw.x, s1 = -tw.y;              // step e^{-i th}
    float c = 1.f, s = 0.f;
    float Xr[4] = {0,0,0,0}, Xi[4] = {0,0,0,0};
    for (int h = 0; h < 64; ++h) {
        #pragma unroll
        for (int jj = 0; jj < 4; ++jj) {
            float2 y = base[h*20 + 5*jj];
            Xr[jj] = fmaf(y.x, c, Xr[jj]);  Xr[jj] = fmaf(-y.y, s, Xr[jj]);
            Xi[jj] = fmaf(y.y, c, Xi[jj]);  Xi[jj] = fmaf(y.x, s, Xi[jj]);
        }
        float cn = fmaf(c, c1, -(s*s1)); s = fmaf(s, c1, c*s1); c = cn;
    }
    #pragma unroll
    for (int jj = 0; jj < 4; ++jj)
        g_X[(size_t)img*800 + r*20 + j0 + 5*jj] = make_float2(Xr[jj], Xi[jj]);
}

// ---------------- stage 3: per-mode complex channel mixing -----------------
__global__ __launch_bounds__(256) void mixk() {
    __shared__ float2 Xs[1024];   // [b*64+i]
    __shared__ float2 Ws[4096];   // [i*64+o]
    int t = threadIdx.x, mo = blockIdx.x;
    for (int u = t; u < 1024; u += 256) Xs[u] = g_X[(size_t)u*800 + mo];
    const float4* wsrc = (const float4*)&g_W[(size_t)mo*4096];
    for (int u = t; u < 2048; u += 256) ((float4*)Ws)[u] = wsrc[u];
    __syncthreads();
    int o = t & 63, b0 = t >> 6;
    float ar[4] = {0,0,0,0}, ai[4] = {0,0,0,0};
    for (int i = 0; i < 64; ++i) {
        float2 Wv = Ws[i*64 + o];
        #pragma unroll
        for (int j = 0; j < 4; ++j) {
            float2 X = Xs[(b0 + 4*j)*64 + i];
            ar[j] = fmaf(X.x, Wv.x, ar[j]);  ar[j] = fmaf(-X.y, Wv.y, ar[j]);
            ai[j] = fmaf(X.x, Wv.y, ai[j]);  ai[j] = fmaf(X.y, Wv.x, ai[j]);
        }
    }
    #pragma unroll
    for (int j = 0; j < 4; ++j) {
        int u = (b0 + 4*j)*64 + o;
        g_O[(size_t)u*800 + mo] = make_float2(ar[j], ai[j]);
    }
}

// ---------------- stage 4: inverse DFT along H (parity split) --------------
__global__ __launch_bounds__(256) void invH() {
    __shared__ float2 Os[800];
    __shared__ float2 Zst[HH*M2];   // 40KB staging
    int t = threadIdx.x, img = blockIdx.x;
    const float2* src = &g_O[(size_t)img*800];
    for (int i = t; i < 800; i += 256) Os[i] = src[i];
    __syncthreads();
    int g = t >> 7, h = t & 127;         // g: k2 group (0..1), h: 0..127
    int kb = g*10;
    float2 st = g_tw[(2*h) & 255];       // step e^{+i 2h th}
    float stc = st.x, sts = st.y;
    float Zer[10], Zei[10], Zor[10], Zoi[10];
    #pragma unroll
    for (int k = 0; k < 10; ++k) { Zer[k]=0.f; Zei[k]=0.f; Zor[k]=0.f; Zoi[k]=0.f; }
    {
        float c = 1.f, s = 0.f;
        #pragma unroll
        for (int rr = 0; rr < 10; ++rr) {
            int r = 2*rr;
            #pragma unroll
            for (int k = 0; k < 10; ++k) {
                float2 O = Os[r*20 + kb + k];
                Zer[k] = fmaf(O.x, c, Zer[k]);  Zer[k] = fmaf(-O.y, s, Zer[k]);
                Zei[k] = fmaf(O.y, c, Zei[k]);  Zei[k] = fmaf(O.x, s, Zei[k]);
            }
            float cn = fmaf(c, stc, -(s*sts)); s = fmaf(s, stc, c*sts); c = cn;
        }
        s = -s;
        #pragma unroll
        for (int rr = 0; rr < 10; ++rr) {
            int r = 20 + 2*rr;
            #pragma unroll
            for (int k = 0; k < 10; ++k) {
                float2 O = Os[r*20 + kb + k];
                Zer[k] = fmaf(O.x, c, Zer[k]);  Zer[k] = fmaf(-O.y, s, Zer[k]);
                Zei[k] = fmaf(O.y, c, Zei[k]);  Zei[k] = fmaf(O.x, s, Zei[k]);
            }
            float cn = fmaf(c, stc, -(s*sts)); s = fmaf(s, stc, c*sts); c = cn;
        }
    }
    {
        float2 t1 = g_tw[h];
        float c = t1.x, s = t1.y;
        #pragma unroll
        for (int rr = 0; rr < 10; ++rr) {
            int r = 1 + 2*rr;
            #pragma unroll
            for (int k = 0; k < 10; ++k) {
                float2 O = Os[r*20 + kb + k];
                Zor[k] = fmaf(O.x, c, Zor[k]);  Zor[k] = fmaf(-O.y, s, Zor[k]);
                Zoi[k] = fmaf(O.y, c, Zoi[k]);  Zoi[k] = fmaf(O.x, s, Zoi[k]);
            }
            if (rr < 9) { float cn = fmaf(c, stc, -(s*sts)); s = fmaf(s, stc, c*sts); c = cn; }
        }
        s = -s;
        #pragma unroll
        for (int rr = 0; rr < 10; ++rr) {
            int r = 21 + 2*rr;
            #pragma unroll
            for (int k = 0; k < 10; ++k) {
                float2 O = Os[r*20 + kb + k];
                Zor[k] = fmaf(O.x, c, Zor[k]);  Zor[k] = fmaf(-O.y, s, Zor[k]);
                Zoi[k] = fmaf(O.y, c, Zoi[k]);  Zoi[k] = fmaf(O.x, s, Zoi[k]);
            }
            float cn = fmaf(c, stc, -(s*sts)); s = fmaf(s, stc, c*sts); c = cn;
        }
    }
    #pragma unroll
    for (int k = 0; k < 10; ++k) {
        Zst[h*20 + kb + k]         = make_float2(Zer[k] + Zor[k], Zei[k] + Zoi[k]);
        Zst[(h + 128)*20 + kb + k] = make_float2(Zer[k] - Zor[k], Zei[k] - Zoi[k]);
    }
    __syncthreads();
    float2* dst = &g_Z[(size_t)img * HH * M2];
    for (int i = t; i < HH*M2; i += 256) dst[i] = Zst[i];
}

// ---------------- stage 5: inverse real DFT along W (fold + table) ---------
__global__ __launch_bounds__(256) void invW(float* __restrict__ out) {
    __shared__ float2 Zs[16*20];
    __shared__ float2 bw[19*64];
    int t = threadIdx.x;
    for (int i = t; i < 320; i += 256) Zs[i] = g_Z[(size_t)blockIdx.x*320 + i];
    for (int i = t; i < 19*64; i += 256) bw[i] = g_basIW[i];
    __syncthreads();
    int rg = t >> 6, wl = t & 63;        // rg 0..3 -> rows rg*4..rg*4+3
    float Ae[4]={0,0,0,0}, Ao[4]={0,0,0,0}, Be[4]={0,0,0,0}, Bo[4]={0,0,0,0};
    #pragma unroll
    for (int k = 1; k < 20; ++k) {
        float2 b = bw[(k-1)*64 + wl];
        if (k & 1) {
            #pragma unroll
            for (int j = 0; j < 4; ++j) {
                float2 Z = Zs[(rg*4 + j)*20 + k];
                Ao[j] = fmaf(Z.x, b.x, Ao[j]);
                Bo[j] = fmaf(Z.y, b.y, Bo[j]);
            }
        } else {
            #pragma unroll
            for (int j = 0; j < 4; ++j) {
                float2 Z = Zs[(rg*4 + j)*20 + k];
                Ae[j] = fmaf(Z.x, b.x, Ae[j]);
                Be[j] = fmaf(Z.y, b.y, Be[j]);
            }
        }
    }
    const float SC = 1.f / 65536.f;
    #pragma unroll
    for (int j = 0; j < 4; ++j) {
        int row = rg*4 + j;
        float base = Zs[row*20].x;       // Im of DC bin ignored (Hermitian)
        float* orow = out + ((size_t)blockIdx.x*16 + row)*256;
        float ap = Ae[j] + Ao[j], am = Ae[j] - Ao[j];
        float bp = Be[j] + Bo[j], bm = Be[j] - Bo[j];
        orow[wl]      = (base + 2.f*(ap - bp)) * SC;            // w (wl=0 -> out[0])
        orow[128-wl]  = (base + 2.f*(am + bm)) * SC;            // 128-w (wl=0 -> out[128])
        if (wl) {
            orow[256-wl] = (base + 2.f*(ap + bp)) * SC;         // 256-w
            orow[128+wl] = (base + 2.f*(am - bm)) * SC;         // 128+w
        } else {
            float a64 = 0.f, b64 = 0.f;
            #pragma unroll
            for (int k = 1; k < 20; ++k) {
                float2 Z = Zs[row*20 + k];
                int m = k & 3;
                if (m == 0)      a64 += Z.x;
                else if (m == 2) a64 -= Z.x;
                else if (m == 1) b64 += Z.y;
                else             b64 -= Z.y;
            }
            orow[64]  = (base + 2.f*(a64 - b64)) * SC;
            orow[192] = (base + 2.f*(a64 + b64)) * SC;
        }
    }
}

extern "C" void kernel_launch(void* const* d_in, const int* in_sizes, int n_in,
                              void* d_out, int out_size) {
    const float* x   = (const float*)d_in[0];
    const float* w1r = (const float*)d_in[1];
    const float* w1i = (const float*)d_in[2];
    const float* w2r = (const float*)d_in[3];
    const float* w2i = (const float*)d_in[4];
    float* out = (float*)d_out;

    wtrans<<<dim3(128, 13, 2), dim3(32, 32)>>>(w1r, w1i, w2r, w2i);  // + table init
    fwdW<<<NROW/32, 160>>>(x);
    fwdH<<<NIMG, 256>>>();
    mixk<<<NRR*M2, 256>>>();        // launch #4 -> profiled
    invH<<<NIMG, 256>>>();
    invW<<<NROW/16, 256>>>(out);
}

// round 10
// speedup vs baseline: 2.0172x; 1.4244x over previous
#include <cuda_runtime.h>

#define BATCH 16
#define CH    64
#define HH    256
#define WW    256
#define M2    20
#define NRR   40
#define NIMG  (BATCH*CH)     /* 1024  */
#define NROW  (NIMG*HH)      /* 262144 */

// ---------------- scratch (device globals; no allocation allowed) ----------
__device__ float2 g_tw[256];          // e^{+2*pi*i*t/256}
__device__ float2 g_Y[NROW*M2];       // forward-W result  [img*256+h][k2]
__device__ float2 g_X[NIMG*NRR*M2];   // forward modes     [img][r][k2]
__device__ float2 g_O[NIMG*NRR*M2];   // mixed modes
__device__ float2 g_W[800*4096];      // transposed weights [mode][i*64+o]

// ---------------- launch 1: twiddle table ----------------------------------
__global__ void initT() {
    int t = threadIdx.x;
    double a = 6.283185307179586476925286766559 * (double)t / 256.0;
    g_tw[t] = make_float2((float)cos(a), (float)sin(a));
}

// ---------------- launches 2,3: weight transpose ----------------------------
__global__ __launch_bounds__(1024) void wtrans(const float* __restrict__ wr, const float* __restrict__ wi,
                                               int base) {
    __shared__ float2 tile[32][33];
    int tx = threadIdx.x, ty = threadIdx.y;
    int u0 = blockIdx.x * 32, o0 = blockIdx.y * 32;
    int off = o0 + tx;
    int u = u0 + ty;
    if (off < 400) tile[ty][tx] = make_float2(wr[u*400 + off], wi[u*400 + off]);
    __syncthreads();
    int offw = o0 + ty;
    if (offw < 400) g_W[(size_t)(base + offw)*4096 + u0 + tx] = tile[tx][ty];
}

// ---------------- stage 1: partial rfft along W (double fold) --------------
__global__ __launch_bounds__(160) void fwdW(const float* __restrict__ x) {
    __shared__ float2 SAB[2*2080 + 2];   // SA rows stride 65; SB at +2082 (bank shift)
    __shared__ float4 SP[32];            // (x0, x128, s64, d64) per row
    float2* SA = SAB;
    float2* SB = SAB + 2082;
    int t = threadIdx.x;
    const float* xb = x + (size_t)blockIdx.x * 8192;   // 32 rows x 256
    for (int i = t; i < 32*63; i += 160) {
        int row = i / 63, w = 1 + (i - row*63);
        const float* xr = xb + row*256;
        float a = xr[w], b = xr[256 - w], cc = xr[128 - w], dd = xr[128 + w];
        float s = a + b, d = a - b, s2 = cc + dd, d2 = cc - dd;
        SA[row*65 + w] = make_float2(s + s2, d - d2);   // (sp, dm)
        SB[row*65 + w] = make_float2(s - s2, d + d2);   // (sm, dp)
    }
    if (t < 32) {
        const float* xr = xb + t*256;
        float x64 = xr[64], x192 = xr[192];
        SP[t] = make_float4(xr[0], xr[128], x64 + x192, x64 - x192);
    }
    __syncthreads();
    int rr = t / 20, k2 = t - 20*rr;          // rr 0..7, k2 0..19
    int oddk = k2 & 1;
    const float2* base = oddk ? SB : SA;
    float f4 = (k2 & 2) ? -1.f : 1.f;
    float2 tw = g_tw[k2];
    float c1 = tw.x, s1 = tw.y, c = c1, s = s1;   // start at w=1
    float ar[4] = {0,0,0,0}, ai[4] = {0,0,0,0};
    for (int w = 1; w < 64; ++w) {
        #pragma unroll
        for (int j = 0; j < 4; ++j) {
            float2 e = base[(rr + 8*j)*65 + w];
            ar[j] = fmaf(e.x, c, ar[j]);
            ai[j] = fmaf(e.y, s, ai[j]);
        }
        float cn = fmaf(c, c1, -(s*s1)); s = fmaf(s, c1, c*s1); c = cn;
    }
    #pragma unroll
    for (int j = 0; j < 4; ++j) {
        int row = rr + 8*j;
        float4 sp = SP[row];
        float re, im;
        if (oddk) { re = ar[j] + sp.x - sp.y;             im = -(ai[j] + f4*sp.w); }
        else      { re = ar[j] + sp.x + sp.y + f4*sp.z;   im = -ai[j]; }
        g_Y[((size_t)blockIdx.x*32 + row)*20 + k2] = make_float2(re, im);
    }
}

// ---------------- stage 2: partial complex DFT along H (radix-4 h-fold) ----
__global__ __launch_bounds__(256) void fwdH() {
    __shared__ float2 Ys[4*1288];   // 4 classes, padded stride 1288 (bank offset 8)
    int t = threadIdx.x, img = blockIdx.x;
    const float2* src = &g_Y[(size_t)img * 5120];
    for (int i = t; i < 5120; i += 256) {
        int m = i / 1280, rsd = i - m*1280;
        Ys[m*1288 + rsd] = src[i];
    }
    __syncthreads();
    for (int i = t; i < 1280; i += 256) {
        float2 a0 = Ys[i], a1 = Ys[1288 + i], a2 = Ys[2576 + i], a3 = Ys[3864 + i];
        float Ax = a0.x - a2.x, Ay = a0.y - a2.y;
        float Bx = a1.x - a3.x, By = a1.y - a3.y;
        float Sx = a0.x + a2.x, Sy = a0.y + a2.y;
        float Tx = a1.x + a3.x, Ty = a1.y + a3.y;
        Ys[i]        = make_float2(Sx + Tx, Sy + Ty);   // q=0
        Ys[1288 + i] = make_float2(Ax + By, Ay - Bx);   // q=1: A - iB
        Ys[2576 + i] = make_float2(Sx - Tx, Sy - Ty);   // q=2
        Ys[3864 + i] = make_float2(Ax - By, Ay + Bx);   // q=3: A + iB
    }
    __syncthreads();
    if (t >= 200) return;
    int r = t / 5, j0 = t - 5*(t/5);          // r 0..39, j0 0..4
    int k1 = r + (r >= 20 ? 216 : 0);
    const float2* base = Ys + (r & 3)*1288 + j0;
    float2 tw = g_tw[k1];
    float c1 = tw.x, s1 = -tw.y;              // step e^{-i th}
    float c = 1.f, s = 0.f;
    float Xr[4] = {0,0,0,0}, Xi[4] = {0,0,0,0};
    for (int h = 0; h < 64; ++h) {
        #pragma unroll
        for (int jj = 0; jj < 4; ++jj) {
            float2 y = base[h*20 + 5*jj];
            Xr[jj] = fmaf(y.x, c, Xr[jj]);  Xr[jj] = fmaf(-y.y, s, Xr[jj]);
            Xi[jj] = fmaf(y.y, c, Xi[jj]);  Xi[jj] = fmaf(y.x, s, Xi[jj]);
        }
        float cn = fmaf(c, c1, -(s*s1)); s = fmaf(s, c1, c*s1); c = cn;
    }
    #pragma unroll
    for (int jj = 0; jj < 4; ++jj)
        g_X[(size_t)img*800 + r*20 + j0 + 5*jj] = make_float2(Xr[jj], Xi[jj]);
}

// ---------------- stage 3: per-mode complex channel mixing (batch-split) ---
__global__ __launch_bounds__(256) void mixk() {
    __shared__ float2 Xs[512];    // [blocal*64+i], blocal 0..7
    __shared__ float2 Ws[4096];   // [i*64+o]
    int t = threadIdx.x, mo = blockIdx.x, half = blockIdx.y;
    for (int u = t; u < 512; u += 256) Xs[u] = g_X[(size_t)(half*512 + u)*800 + mo];
    const float4* wsrc = (const float4*)&g_W[(size_t)mo*4096];
    for (int u = t; u < 2048; u += 256) ((float4*)Ws)[u] = wsrc[u];
    __syncthreads();
    int o = t & 63, b0 = t >> 6;              // b0 0..3
    float ar[2] = {0,0}, ai[2] = {0,0};
    for (int i = 0; i < 64; ++i) {
        float2 Wv = Ws[i*64 + o];
        #pragma unroll
        for (int j = 0; j < 2; ++j) {
            float2 X = Xs[(b0 + 4*j)*64 + i];
            ar[j] = fmaf(X.x, Wv.x, ar[j]);  ar[j] = fmaf(-X.y, Wv.y, ar[j]);
            ai[j] = fmaf(X.x, Wv.y, ai[j]);  ai[j] = fmaf(X.y, Wv.x, ai[j]);
        }
    }
    #pragma unroll
    for (int j = 0; j < 2; ++j) {
        int u = (half*8 + b0 + 4*j)*64 + o;
        g_O[(size_t)u*800 + mo] = make_float2(ar[j], ai[j]);
    }
}

// ---------------- stage 4+5 fused: inverse H then inverse real W -----------
__global__ __launch_bounds__(256) void invHW(float* __restrict__ out) {
    __shared__ float2 Os[800];
    __shared__ float2 Zst[HH*M2];   // 40KB staging, lives through both phases
    int t = threadIdx.x, img = blockIdx.x;
    const float2* src = &g_O[(size_t)img*800];
    for (int i = t; i < 800; i += 256) Os[i] = src[i];
    __syncthreads();
    // ---- phase 1: inverse DFT along H (parity split), Z -> Zst ----
    {
        int g = t >> 7, h = t & 127;
        int kb = g*10;
        float2 st = g_tw[(2*h) & 255];
        float stc = st.x, sts = st.y;
        float Zer[10], Zei[10], Zor[10], Zoi[10];
        #pragma unroll
        for (int k = 0; k < 10; ++k) { Zer[k]=0.f; Zei[k]=0.f; Zor[k]=0.f; Zoi[k]=0.f; }
        {
            float c = 1.f, s = 0.f;
            #pragma unroll
            for (int rr = 0; rr < 10; ++rr) {
                int r = 2*rr;
                #pragma unroll
                for (int k = 0; k < 10; ++k) {
                    float2 O = Os[r*20 + kb + k];
                    Zer[k] = fmaf(O.x, c, Zer[k]);  Zer[k] = fmaf(-O.y, s, Zer[k]);
                    Zei[k] = fmaf(O.y, c, Zei[k]);  Zei[k] = fmaf(O.x, s, Zei[k]);
                }
                float cn = fmaf(c, stc, -(s*sts)); s = fmaf(s, stc, c*sts); c = cn;
            }
            s = -s;
            #pragma unroll
            for (int rr = 0; rr < 10; ++rr) {
                int r = 20 + 2*rr;
                #pragma unroll
                for (int k = 0; k < 10; ++k) {
                    float2 O = Os[r*20 + kb + k];
                    Zer[k] = fmaf(O.x, c, Zer[k]);  Zer[k] = fmaf(-O.y, s, Zer[k]);
                    Zei[k] = fmaf(O.y, c, Zei[k]);  Zei[k] = fmaf(O.x, s, Zei[k]);
                }
                float cn = fmaf(c, stc, -(s*sts)); s = fmaf(s, stc, c*sts); c = cn;
            }
        }
        {
            float2 t1 = g_tw[t & 127];
            float c = t1.x, s = t1.y;
            #pragma unroll
            for (int rr = 0; rr < 10; ++rr) {
                int r = 1 + 2*rr;
                #pragma unroll
                for (int k = 0; k < 10; ++k) {
                    float2 O = Os[r*20 + kb + k];
                    Zor[k] = fmaf(O.x, c, Zor[k]);  Zor[k] = fmaf(-O.y, s, Zor[k]);
                    Zoi[k] = fmaf(O.y, c, Zoi[k]);  Zoi[k] = fmaf(O.x, s, Zoi[k]);
                }
                if (rr < 9) { float cn = fmaf(c, stc, -(s*sts)); s = fmaf(s, stc, c*sts); c = cn; }
            }
            s = -s;
            #pragma unroll
            for (int rr = 0; rr < 10; ++rr) {
                int r = 21 + 2*rr;
                #pragma unroll
                for (int k = 0; k < 10; ++k) {
                    float2 O = Os[r*20 + kb + k];
                    Zor[k] = fmaf(O.x, c, Zor[k]);  Zor[k] = fmaf(-O.y, s, Zor[k]);
                    Zoi[k] = fmaf(O.y, c, Zoi[k]);  Zoi[k] = fmaf(O.x, s, Zoi[k]);
                }
                float cn = fmaf(c, stc, -(s*sts)); s = fmaf(s, stc, c*sts); c = cn;
            }
        }
        #pragma unroll
        for (int k = 0; k < 10; ++k) {
            Zst[h*20 + kb + k]         = make_float2(Zer[k] + Zor[k], Zei[k] + Zoi[k]);
            Zst[(h + 128)*20 + kb + k] = make_float2(Zer[k] - Zor[k], Zei[k] - Zoi[k]);
        }
    }
    __syncthreads();
    // ---- phase 2: inverse real DFT along W (k-parity fold), 16 passes ----
    int rg = t >> 6, wl = t & 63;
    float2 tww = g_tw[wl];
    float cw = tww.x, sw = tww.y;
    const float SC = 1.f / 65536.f;
    float* obase = out + (size_t)img * 65536;
    for (int p = 0; p < 16; ++p) {
        int rb = p*16 + rg*4;
        float Ae[4]={0,0,0,0}, Ao[4]={0,0,0,0}, Be[4]={0,0,0,0}, Bo[4]={0,0,0,0};
        float c = cw, s = sw;
        #pragma unroll
        for (int k = 1; k < 20; ++k) {
            if (k & 1) {
                #pragma unroll
                for (int j = 0; j < 4; ++j) {
                    float2 Z = Zst[(rb + j)*20 + k];
                    Ao[j] = fmaf(Z.x, c, Ao[j]);
                    Bo[j] = fmaf(Z.y, s, Bo[j]);
                }
            } else {
                #pragma unroll
                for (int j = 0; j < 4; ++j) {
                    float2 Z = Zst[(rb + j)*20 + k];
                    Ae[j] = fmaf(Z.x, c, Ae[j]);
                    Be[j] = fmaf(Z.y, s, Be[j]);
                }
            }
            float cn = fmaf(c, cw, -(s*sw)); s = fmaf(s, cw, c*sw); c = cn;
        }
        #pragma unroll
        for (int j = 0; j < 4; ++j) {
            int row = rb + j;
            float base = Zst[row*20].x;      // Im of DC bin ignored (Hermitian)
            float* orow = obase + row*256;
            float ap = Ae[j] + Ao[j], am = Ae[j] - Ao[j];
            float bp = Be[j] + Bo[j], bm = Be[j] - Bo[j];
            orow[wl]     = (base + 2.f*(ap - bp)) * SC;   // w   (wl=0 -> out[0])
            orow[128-wl] = (base + 2.f*(am + bm)) * SC;   // 128-w (wl=0 -> out[128])
            if (wl) {
                orow[256-wl] = (base + 2.f*(ap + bp)) * SC;
                orow[128+wl] = (base + 2.f*(am - bm)) * SC;
            } else {
                float a64 = 0.f, b64 = 0.f;
                #pragma unroll
                for (int k = 1; k < 20; ++k) {
                    float2 Z = Zst[row*20 + k];
                    int m = k & 3;
                    if (m == 0)      a64 += Z.x;
                    else if (m == 2) a64 -= Z.x;
                    else if (m == 1) b64 += Z.y;
                    else             b64 -= Z.y;
                }
                orow[64]  = (base + 2.f*(a64 - b64)) * SC;
                orow[192] = (base + 2.f*(a64 + b64)) * SC;
            }
        }
    }
}

extern "C" void kernel_launch(void* const* d_in, const int* in_sizes, int n_in,
                              void* d_out, int out_size) {
    const float* x   = (const float*)d_in[0];
    const float* w1r = (const float*)d_in[1];
    const float* w1i = (const float*)d_in[2];
    const float* w2r = (const float*)d_in[3];
    const float* w2i = (const float*)d_in[4];
    float* out = (float*)d_out;

    initT<<<1, 256>>>();
    wtrans<<<dim3(128, 13), dim3(32, 32)>>>(w1r, w1i, 0);
    wtrans<<<dim3(128, 13), dim3(32, 32)>>>(w2r, w2i, 400);
    fwdW<<<NROW/32, 160>>>(x);                 // launch #4 -> profiled
    fwdH<<<NIMG, 256>>>();
    mixk<<<dim3(NRR*M2, 2), 256>>>();
    invHW<<<NIMG, 256>>>(out);
}

// round 11
// speedup vs baseline: 2.1320x; 1.0569x over previous
#include <cuda_runtime.h>

#define BATCH 16
#define CH    64
#define HH    256
#define WW    256
#define M2    20
#define NRR   40
#define NIMG  (BATCH*CH)     /* 1024  */
#define NROW  (NIMG*HH)      /* 262144 */

// ---------------- scratch (device globals; no allocation allowed) ----------
__device__ float2 g_tw[256];          // e^{+2*pi*i*t/256}
__device__ float2 g_Y[NROW*M2];       // forward-W result  [img*256+h][k2]
__device__ float2 g_X[NIMG*NRR*M2];   // forward modes     [img][r][k2]
__device__ float2 g_O[NIMG*NRR*M2];   // mixed modes
__device__ float2 g_W[800*4096];      // transposed weights [mode][i*64+o]

// ---------------- launch 1: twiddle table ----------------------------------
__global__ void initT() {
    int t = threadIdx.x;
    double a = 6.283185307179586476925286766559 * (double)t / 256.0;
    g_tw[t] = make_float2((float)cos(a), (float)sin(a));
}

// ---------------- launches 2,3: weight transpose ----------------------------
__global__ __launch_bounds__(1024) void wtrans(const float* __restrict__ wr, const float* __restrict__ wi,
                                               int base) {
    __shared__ float2 tile[32][33];
    int tx = threadIdx.x, ty = threadIdx.y;
    int u0 = blockIdx.x * 32, o0 = blockIdx.y * 32;
    int off = o0 + tx;
    int u = u0 + ty;
    if (off < 400) tile[ty][tx] = make_float2(wr[u*400 + off], wi[u*400 + off]);
    __syncthreads();
    int offw = o0 + ty;
    if (offw < 400) g_W[(size_t)(base + offw)*4096 + u0 + tx] = tile[tx][ty];
}

// ---------------- stage 1: partial rfft along W (double fold) --------------
// 320 threads: 16 rr-groups x 20 k2; each thread 2 rows (rr, rr+16).
__global__ __launch_bounds__(320) void fwdW(const float* __restrict__ x) {
    __shared__ float2 SAB[2*2080 + 2];   // SA rows stride 65; SB at +2082 (bank shift)
    __shared__ float4 SP[32];            // (x0, x128, s64, d64) per row
    float2* SA = SAB;
    float2* SB = SAB + 2082;
    int t = threadIdx.x;
    const float* xb = x + (size_t)blockIdx.x * 8192;   // 32 rows x 256
    for (int i = t; i < 2048; i += 320) {
        int row = i >> 6, w = i & 63;
        const float* xr = xb + row*256;
        if (w) {
            float a = xr[w], b = xr[256 - w], cc = xr[128 - w], dd = xr[128 + w];
            float s = a + b, d = a - b, s2 = cc + dd, d2 = cc - dd;
            SA[row*65 + w] = make_float2(s + s2, d - d2);   // (sp, dm)
            SB[row*65 + w] = make_float2(s - s2, d + d2);   // (sm, dp)
        } else {
            float x64 = xr[64], x192 = xr[192];
            SP[row] = make_float4(xr[0], xr[128], x64 + x192, x64 - x192);
        }
    }
    __syncthreads();
    int rr = t / 20, k2 = t - 20*(t/20);      // rr 0..15, k2 0..19
    int oddk = k2 & 1;
    const float2* base = oddk ? SB : SA;
    float f4 = (k2 & 2) ? -1.f : 1.f;
    float2 tw = g_tw[k2];
    float c1 = tw.x, s1 = tw.y, c = c1, s = s1;   // start at w=1
    float ar[2] = {0,0}, ai[2] = {0,0};
    for (int w = 1; w < 64; ++w) {
        #pragma unroll
        for (int j = 0; j < 2; ++j) {
            float2 e = base[(rr + 16*j)*65 + w];
            ar[j] = fmaf(e.x, c, ar[j]);
            ai[j] = fmaf(e.y, s, ai[j]);
        }
        float cn = fmaf(c, c1, -(s*s1)); s = fmaf(s, c1, c*s1); c = cn;
    }
    #pragma unroll
    for (int j = 0; j < 2; ++j) {
        int row = rr + 16*j;
        float4 sp = SP[row];
        float re, im;
        if (oddk) { re = ar[j] + sp.x - sp.y;             im = -(ai[j] + f4*sp.w); }
        else      { re = ar[j] + sp.x + sp.y + f4*sp.z;   im = -ai[j]; }
        g_Y[((size_t)blockIdx.x*32 + row)*20 + k2] = make_float2(re, im);
    }
}

// ---------------- stage 2: partial complex DFT along H (radix-4 h-fold) ----
__global__ __launch_bounds__(256) void fwdH() {
    __shared__ float2 Ys[4*1288];   // 4 classes, padded stride 1288 (bank offset 8)
    int t = threadIdx.x, img = blockIdx.x;
    const float2* src = &g_Y[(size_t)img * 5120];
    for (int i = t; i < 5120; i += 256) {
        int m = i / 1280, rsd = i - m*1280;
        Ys[m*1288 + rsd] = src[i];
    }
    __syncthreads();
    for (int i = t; i < 1280; i += 256) {
        float2 a0 = Ys[i], a1 = Ys[1288 + i], a2 = Ys[2576 + i], a3 = Ys[3864 + i];
        float Ax = a0.x - a2.x, Ay = a0.y - a2.y;
        float Bx = a1.x - a3.x, By = a1.y - a3.y;
        float Sx = a0.x + a2.x, Sy = a0.y + a2.y;
        float Tx = a1.x + a3.x, Ty = a1.y + a3.y;
        Ys[i]        = make_float2(Sx + Tx, Sy + Ty);   // q=0
        Ys[1288 + i] = make_float2(Ax + By, Ay - Bx);   // q=1: A - iB
        Ys[2576 + i] = make_float2(Sx - Tx, Sy - Ty);   // q=2
        Ys[3864 + i] = make_float2(Ax - By, Ay + Bx);   // q=3: A + iB
    }
    __syncthreads();
    if (t >= 200) return;
    int r = t / 5, j0 = t - 5*(t/5);          // r 0..39, j0 0..4
    int k1 = r + (r >= 20 ? 216 : 0);
    const float2* base = Ys + (r & 3)*1288 + j0;
    float2 tw = g_tw[k1];
    float c1 = tw.x, s1 = -tw.y;              // step e^{-i th}
    float c = 1.f, s = 0.f;
    float Xr[4] = {0,0,0,0}, Xi[4] = {0,0,0,0};
    for (int h = 0; h < 64; ++h) {
        #pragma unroll
        for (int jj = 0; jj < 4; ++jj) {
            float2 y = base[h*20 + 5*jj];
            Xr[jj] = fmaf(y.x, c, Xr[jj]);  Xr[jj] = fmaf(-y.y, s, Xr[jj]);
            Xi[jj] = fmaf(y.y, c, Xi[jj]);  Xi[jj] = fmaf(y.x, s, Xi[jj]);
        }
        float cn = fmaf(c, c1, -(s*s1)); s = fmaf(s, c1, c*s1); c = cn;
    }
    #pragma unroll
    for (int jj = 0; jj < 4; ++jj)
        g_X[(size_t)img*800 + r*20 + j0 + 5*jj] = make_float2(Xr[jj], Xi[jj]);
}

// ---------------- stage 3: per-mode complex channel mixing (batch-split) ---
__global__ __launch_bounds__(256) void mixk() {
    __shared__ float2 Xs[512];    // [blocal*64+i], blocal 0..7
    __shared__ float2 Ws[4096];   // [i*64+o]
    int t = threadIdx.x, mo = blockIdx.x, half = blockIdx.y;
    for (int u = t; u < 512; u += 256) Xs[u] = g_X[(size_t)(half*512 + u)*800 + mo];
    const float4* wsrc = (const float4*)&g_W[(size_t)mo*4096];
    for (int u = t; u < 2048; u += 256) ((float4*)Ws)[u] = wsrc[u];
    __syncthreads();
    int o = t & 63, b0 = t >> 6;              // b0 0..3
    float ar[2] = {0,0}, ai[2] = {0,0};
    for (int i = 0; i < 64; ++i) {
        float2 Wv = Ws[i*64 + o];
        #pragma unroll
        for (int j = 0; j < 2; ++j) {
            float2 X = Xs[(b0 + 4*j)*64 + i];
            ar[j] = fmaf(X.x, Wv.x, ar[j]);  ar[j] = fmaf(-X.y, Wv.y, ar[j]);
            ai[j] = fmaf(X.x, Wv.y, ai[j]);  ai[j] = fmaf(X.y, Wv.x, ai[j]);
        }
    }
    #pragma unroll
    for (int j = 0; j < 2; ++j) {
        int u = (half*8 + b0 + 4*j)*64 + o;
        g_O[(size_t)u*800 + mo] = make_float2(ar[j], ai[j]);
    }
}

// ---------------- stage 4+5 fused: inverse H then inverse real W -----------
__global__ __launch_bounds__(256) void invHW(float* __restrict__ out) {
    __shared__ float2 Os[800];
    __shared__ float2 Zst[HH*M2];   // 40KB staging, lives through both phases
    int t = threadIdx.x, img = blockIdx.x;
    const float2* src = &g_O[(size_t)img*800];
    for (int i = t; i < 800; i += 256) Os[i] = src[i];
    __syncthreads();
    // ---- phase 1: inverse DFT along H (parity split), Z -> Zst ----
    {
        int g = t >> 7, h = t & 127;
        int kb = g*10;
        float2 st = g_tw[(2*h) & 255];
        float stc = st.x, sts = st.y;
        float Zer[10], Zei[10], Zor[10], Zoi[10];
        #pragma unroll
        for (int k = 0; k < 10; ++k) { Zer[k]=0.f; Zei[k]=0.f; Zor[k]=0.f; Zoi[k]=0.f; }
        {
            float c = 1.f, s = 0.f;
            #pragma unroll
            for (int rr = 0; rr < 10; ++rr) {
                int r = 2*rr;
                #pragma unroll
                for (int k = 0; k < 10; ++k) {
                    float2 O = Os[r*20 + kb + k];
                    Zer[k] = fmaf(O.x, c, Zer[k]);  Zer[k] = fmaf(-O.y, s, Zer[k]);
                    Zei[k] = fmaf(O.y, c, Zei[k]);  Zei[k] = fmaf(O.x, s, Zei[k]);
                }
                float cn = fmaf(c, stc, -(s*sts)); s = fmaf(s, stc, c*sts); c = cn;
            }
            s = -s;
            #pragma unroll
            for (int rr = 0; rr < 10; ++rr) {
                int r = 20 + 2*rr;
                #pragma unroll
                for (int k = 0; k < 10; ++k) {
                    float2 O = Os[r*20 + kb + k];
                    Zer[k] = fmaf(O.x, c, Zer[k]);  Zer[k] = fmaf(-O.y, s, Zer[k]);
                    Zei[k] = fmaf(O.y, c, Zei[k]);  Zei[k] = fmaf(O.x, s, Zei[k]);
                }
                float cn = fmaf(c, stc, -(s*sts)); s = fmaf(s, stc, c*sts); c = cn;
            }
        }
        {
            float2 t1 = g_tw[t & 127];
            float c = t1.x, s = t1.y;
            #pragma unroll
            for (int rr = 0; rr < 10; ++rr) {
                int r = 1 + 2*rr;
                #pragma unroll
                for (int k = 0; k < 10; ++k) {
                    float2 O = Os[r*20 + kb + k];
                    Zor[k] = fmaf(O.x, c, Zor[k]);  Zor[k] = fmaf(-O.y, s, Zor[k]);
                    Zoi[k] = fmaf(O.y, c, Zoi[k]);  Zoi[k] = fmaf(O.x, s, Zoi[k]);
                }
                if (rr < 9) { float cn = fmaf(c, stc, -(s*sts)); s = fmaf(s, stc, c*sts); c = cn; }
            }
            s = -s;
            #pragma unroll
            for (int rr = 0; rr < 10; ++rr) {
                int r = 21 + 2*rr;
                #pragma unroll
                for (int k = 0; k < 10; ++k) {
                    float2 O = Os[r*20 + kb + k];
                    Zor[k] = fmaf(O.x, c, Zor[k]);  Zor[k] = fmaf(-O.y, s, Zor[k]);
                    Zoi[k] = fmaf(O.y, c, Zoi[k]);  Zoi[k] = fmaf(O.x, s, Zoi[k]);
                }
                float cn = fmaf(c, stc, -(s*sts)); s = fmaf(s, stc, c*sts); c = cn;
            }
        }
        #pragma unroll
        for (int k = 0; k < 10; ++k) {
            Zst[h*20 + kb + k]         = make_float2(Zer[k] + Zor[k], Zei[k] + Zoi[k]);
            Zst[(h + 128)*20 + kb + k] = make_float2(Zer[k] - Zor[k], Zei[k] - Zoi[k]);
        }
    }
    __syncthreads();
    // ---- phase 2: inverse real DFT along W (k-parity fold), 16 passes ----
    int rg = t >> 6, wl = t & 63;
    float2 tww = g_tw[wl];
    float cw = tww.x, sw = tww.y;
    const float SC = 1.f / 65536.f;
    float* obase = out + (size_t)img * 65536;
    for (int p = 0; p < 16; ++p) {
        int rb = p*16 + rg*4;
        float Ae[4]={0,0,0,0}, Ao[4]={0,0,0,0}, Be[4]={0,0,0,0}, Bo[4]={0,0,0,0};
        float c = cw, s = sw;
        #pragma unroll
        for (int k = 1; k < 20; ++k) {
            if (k & 1) {
                #pragma unroll
                for (int j = 0; j < 4; ++j) {
                    float2 Z = Zst[(rb + j)*20 + k];
                    Ao[j] = fmaf(Z.x, c, Ao[j]);
                    Bo[j] = fmaf(Z.y, s, Bo[j]);
                }
            } else {
                #pragma unroll
                for (int j = 0; j < 4; ++j) {
                    float2 Z = Zst[(rb + j)*20 + k];
                    Ae[j] = fmaf(Z.x, c, Ae[j]);
                    Be[j] = fmaf(Z.y, s, Be[j]);
                }
            }
            float cn = fmaf(c, cw, -(s*sw)); s = fmaf(s, cw, c*sw); c = cn;
        }
        #pragma unroll
        for (int j = 0; j < 4; ++j) {
            int row = rb + j;
            float base = Zst[row*20].x;      // Im of DC bin ignored (Hermitian)
            float* orow = obase + row*256;
            float ap = Ae[j] + Ao[j], am = Ae[j] - Ao[j];
            float bp = Be[j] + Bo[j], bm = Be[j] - Bo[j];
            orow[wl]     = (base + 2.f*(ap - bp)) * SC;   // w   (wl=0 -> out[0])
            orow[128-wl] = (base + 2.f*(am + bm)) * SC;   // 128-w (wl=0 -> out[128])
            if (wl) {
                orow[256-wl] = (base + 2.f*(ap + bp)) * SC;
                orow[128+wl] = (base + 2.f*(am - bm)) * SC;
            } else {
                float a64 = 0.f, b64 = 0.f;
                #pragma unroll
                for (int k = 1; k < 20; ++k) {
                    float2 Z = Zst[row*20 + k];
                    int m = k & 3;
                    if (m == 0)      a64 += Z.x;
                    else if (m == 2) a64 -= Z.x;
                    else if (m == 1) b64 += Z.y;
                    else             b64 -= Z.y;
                }
                orow[64]  = (base + 2.f*(a64 - b64)) * SC;
                orow[192] = (base + 2.f*(a64 + b64)) * SC;
            }
        }
    }
}

extern "C" void kernel_launch(void* const* d_in, const int* in_sizes, int n_in,
                              void* d_out, int out_size) {
    const float* x   = (const float*)d_in[0];
    const float* w1r = (const float*)d_in[1];
    const float* w1i = (const float*)d_in[2];
    const float* w2r = (const float*)d_in[3];
    const float* w2i = (const float*)d_in[4];
    float* out = (float*)d_out;

    initT<<<1, 256>>>();
    wtrans<<<dim3(128, 13), dim3(32, 32)>>>(w1r, w1i, 0);
    wtrans<<<dim3(128, 13), dim3(32, 32)>>>(w2r, w2i, 400);
    fwdW<<<NROW/32, 320>>>(x);                 // launch #4 -> profiled
    fwdH<<<NIMG, 256>>>();
    mixk<<<dim3(NRR*M2, 2), 256>>>();
    invHW<<<NIMG, 256>>>(out);
}